// round 2
// baseline (speedup 1.0000x reference)
#include <cuda_runtime.h>
#include <cuda_bf16.h>
#include <cstdint>

#define DEV_INLINE __device__ __forceinline__

static constexpr int M_DIM = 8192;
static constexpr int N_DIM = 4096;
static constexpr int K_DIM = 4096;
static constexpr int K_BYTES = K_DIM * 2;          // bf16 row bytes

static constexpr float FP8_MAX_F  = 448.0f;
static constexpr float AMAX_EPS_F = 1e-8f;
static constexpr float MOMENTUM_F = 0.95f;

// tcgen05 only exists when an arch-specific ('a') target is compiled.
#if defined(__CUDA_ARCH_FEAT_SM103_ALL) || defined(__CUDA_ARCH_FEAT_SM100_ALL)
#define HAS_TCGEN05 1
#else
#define HAS_TCGEN05 0
#endif

// -------- scratch (allocation-free: device globals) --------
__device__ __align__(16) __nv_bfloat16 g_xq[(size_t)M_DIM * K_DIM];  // 64 MB
__device__ __align__(16) __nv_bfloat16 g_wq[(size_t)N_DIM * K_DIM];  // 32 MB
__device__ unsigned int g_amax_bits[2];

// ======================= helpers =======================
DEV_INLINE uint32_t smem_u32(const void* p) {
    uint32_t r;
    asm("{ .reg .u64 t; cvta.to.shared.u64 t, %1; cvt.u32.u64 %0, t; }" : "=r"(r) : "l"(p));
    return r;
}
DEV_INLINE void cp_async16(uint32_t smem, const void* gmem) {
    asm volatile("cp.async.cg.shared.global [%0], [%1], 16;\n" :: "r"(smem), "l"(gmem));
}
DEV_INLINE uint32_t sw128(uint32_t off) { return off ^ ((off >> 3) & 0x70); }

// ======================= kernel 0: init amax scratch =======================
__global__ void init_amax_kernel(unsigned int* bits) {
    if (threadIdx.x < 2) bits[threadIdx.x] = 0u;
}

// ======================= kernel 1: quantize + amax =======================
// fp32 -> clamp/scale -> e4m3 (exact rn.satfinite) -> back to bf16 (exact).
// Stores the *scaled-domain* q values (|v| <= 448); epilogue multiplies by
// (amax_x*amax_w)/448^2.
__global__ void __launch_bounds__(256) quant_kernel(
    const float* __restrict__ in, __nv_bfloat16* __restrict__ outq,
    const float* __restrict__ amax_in, unsigned int* __restrict__ amax_bits)
{
    const int idx = blockIdx.x * blockDim.x + threadIdx.x;
    const float scale = FP8_MAX_F / fmaxf(__ldg(amax_in), AMAX_EPS_F);

    const float4* p = reinterpret_cast<const float4*>(in) + (size_t)idx * 2;
    float4 v0 = p[0], v1 = p[1];
    float vals[8] = {v0.x, v0.y, v0.z, v0.w, v1.x, v1.y, v1.z, v1.w};

    float m = 0.0f;
    #pragma unroll
    for (int i = 0; i < 8; i++) m = fmaxf(m, fabsf(vals[i]));

    uint32_t packed[4];
    #pragma unroll
    for (int i = 0; i < 4; i++) {
        unsigned short e;
        // first src -> high byte, second -> low byte
        asm("cvt.rn.satfinite.e4m3x2.f32 %0, %1, %2;"
            : "=h"(e) : "f"(vals[2*i+1] * scale), "f"(vals[2*i] * scale));
        uint32_t h2;
        asm("cvt.rn.f16x2.e4m3x2 %0, %1;" : "=r"(h2) : "h"(e));
        float flo, fhi;
        asm("{ .reg .f16 a, b; mov.b32 {a, b}, %2; cvt.f32.f16 %0, a; cvt.f32.f16 %1, b; }"
            : "=f"(flo), "=f"(fhi) : "r"(h2));
        // first src -> high half, second -> low half
        asm("cvt.rn.bf16x2.f32 %0, %1, %2;" : "=r"(packed[i]) : "f"(fhi), "f"(flo));
    }
    uint4 outv = {packed[0], packed[1], packed[2], packed[3]};
    reinterpret_cast<uint4*>(outq)[idx] = outv;

    #pragma unroll
    for (int o = 16; o > 0; o >>= 1) m = fmaxf(m, __shfl_xor_sync(0xffffffff, m, o));
    __shared__ float wmax[8];
    if ((threadIdx.x & 31) == 0) wmax[threadIdx.x >> 5] = m;
    __syncthreads();
    if (threadIdx.x == 0) {
        float t = wmax[0];
        #pragma unroll
        for (int i = 1; i < 8; i++) t = fmaxf(t, wmax[i]);
        atomicMax(amax_bits, __float_as_uint(t));
    }
}

// ======================= kernel 2: amax EMA finalize =======================
__global__ void finalize_amax_kernel(
    const float* __restrict__ in_amax, const float* __restrict__ w_amax,
    const unsigned int* __restrict__ bits, float* __restrict__ tail)
{
    if (threadIdx.x == 0) {
        float ax = __uint_as_float(bits[0]);
        float aw = __uint_as_float(bits[1]);
        if (!(ax == ax)) ax = AMAX_EPS_F;
        if (isinf(ax))   ax = FP8_MAX_F;
        if (!(aw == aw)) aw = AMAX_EPS_F;
        if (isinf(aw))   aw = FP8_MAX_F;
        tail[0] = fmaxf(fmaxf(__ldg(in_amax) * MOMENTUM_F, ax), AMAX_EPS_F);
        tail[1] = fmaxf(fmaxf(__ldg(w_amax)  * MOMENTUM_F, aw), AMAX_EPS_F);
    }
}

// ======================= GEMM =======================
static constexpr int BM = 128, BN = 128, BK = 64, NSTAGE = 3;
static constexpr int NKT = K_DIM / BK;                  // 64
static constexpr int A_TILE_BYTES = BM * BK * 2;        // 16384
static constexpr int STAGE_BYTES  = 2 * A_TILE_BYTES;   // 32768 (A then B)
static constexpr int SMEM_HEAD  = 1024;                 // mbarriers + tmem ptr
static constexpr int SMEM_TOTAL = SMEM_HEAD + NSTAGE * STAGE_BYTES;  // 99328

// shared loader: one BK=64 slab of A(128 rows) + B(128 rows), SW128-swizzled
DEV_INLINE void load_stage(uint32_t sA, const __nv_bfloat16* gA,
                           const __nv_bfloat16* gB, int kt, int tid)
{
    const char* pA = (const char*)gA + (size_t)kt * (BK * 2);
    const char* pB = (const char*)gB + (size_t)kt * (BK * 2);
    #pragma unroll
    for (int i = 0; i < 4; i++) {
        int chunk = tid + i * 256;               // 0..1023
        int row = chunk >> 3, colb = (chunk & 7) << 4;
        uint32_t sw = sw128((uint32_t)(row * 128 + colb));
        cp_async16(sA + sw, pA + (size_t)row * K_BYTES + colb);
    }
    const uint32_t sB = sA + A_TILE_BYTES;
    #pragma unroll
    for (int i = 0; i < 4; i++) {
        int chunk = tid + i * 256;
        int row = chunk >> 3, colb = (chunk & 7) << 4;
        uint32_t sw = sw128((uint32_t)(row * 128 + colb));
        cp_async16(sB + sw, pB + (size_t)row * K_BYTES + colb);
    }
    asm volatile("cp.async.commit_group;\n" ::: "memory");
}

#if HAS_TCGEN05
// ---- tcgen05 helpers (compiled only for 'a' targets) ----
DEV_INLINE uint32_t elect_one() {
    uint32_t p;
    asm volatile("{ .reg .pred p; elect.sync _|p, 0xFFFFFFFF; selp.b32 %0,1,0,p; }" : "=r"(p));
    return p;
}
static constexpr uint64_t SMEM_DESC_BASE_SW128 =
    (uint64_t(2) << 61) | (uint64_t(1) << 46) | (uint64_t(64) << 32) | (uint64_t(1) << 16);
#define MAKE_SMEM_DESC(base_addr) \
    (SMEM_DESC_BASE_SW128 | ((uint64_t)((base_addr) >> 4) & 0x3FFF))
// kind::f16 idesc: F32 out, BF16 x BF16, N=128, M=128
static constexpr uint32_t IDESC_F16 =
    (1u << 4) | (1u << 7) | (1u << 10) | ((BN / 8) << 17) | ((BM / 16) << 24);

DEV_INLINE void mma_f16_ss(uint32_t d_tmem, uint64_t a_desc, uint64_t b_desc,
                           uint32_t idesc, uint32_t enable) {
    asm volatile(
        "{\n\t"
        ".reg .pred p;\n\t"
        "setp.ne.u32 p, %5, 0;\n\t"
        "tcgen05.mma.cta_group::1.kind::f16 [%0], %1, %2, %3, {%4, %4, %4, %4}, p;\n\t"
        "}"
        :: "r"(d_tmem), "l"(a_desc), "l"(b_desc), "r"(idesc), "r"(0u), "r"(enable)
        : "memory");
}
#define MBARRIER_INIT(mbar, count) \
    asm volatile("mbarrier.init.shared.b64 [%0], %1;" \
        :: "r"((uint32_t)(mbar)), "r"((uint32_t)(count)) : "memory")
#define MBARRIER_WAIT_PARITY(mbar_addr, parity) do { \
    uint32_t _mbar = (uint32_t)(mbar_addr); \
    uint32_t _par = (uint32_t)(parity); \
    asm volatile( \
        "{\n\t.reg .pred P1;\n\t" \
        "WAIT_LOOP_%=:\n\t" \
        "mbarrier.try_wait.parity.acquire.cta.shared::cta.b64 P1, [%0], %1, 0x989680;\n\t" \
        "@P1 bra.uni WAIT_DONE_%=;\n\t" \
        "bra.uni WAIT_LOOP_%=;\n\t" \
        "WAIT_DONE_%=:\n\t}" \
        :: "r"(_mbar), "r"(_par) : "memory"); \
} while (0)
#define TCGEN05_LD_32X32B_X32(r, tmem_addr) \
    asm volatile( \
        "tcgen05.ld.sync.aligned.32x32b.x32.b32 " \
        "{%0, %1, %2, %3, %4, %5, %6, %7, " \
        " %8, %9, %10, %11, %12, %13, %14, %15, " \
        " %16, %17, %18, %19, %20, %21, %22, %23, " \
        " %24, %25, %26, %27, %28, %29, %30, %31}, [%32];" \
        : "=r"((r)[0]),  "=r"((r)[1]),  "=r"((r)[2]),  "=r"((r)[3]), \
          "=r"((r)[4]),  "=r"((r)[5]),  "=r"((r)[6]),  "=r"((r)[7]), \
          "=r"((r)[8]),  "=r"((r)[9]),  "=r"((r)[10]), "=r"((r)[11]), \
          "=r"((r)[12]), "=r"((r)[13]), "=r"((r)[14]), "=r"((r)[15]), \
          "=r"((r)[16]), "=r"((r)[17]), "=r"((r)[18]), "=r"((r)[19]), \
          "=r"((r)[20]), "=r"((r)[21]), "=r"((r)[22]), "=r"((r)[23]), \
          "=r"((r)[24]), "=r"((r)[25]), "=r"((r)[26]), "=r"((r)[27]), \
          "=r"((r)[28]), "=r"((r)[29]), "=r"((r)[30]), "=r"((r)[31]) \
        : "r"(tmem_addr))
#endif  // HAS_TCGEN05

#if !HAS_TCGEN05
DEV_INLINE void mma_bf16(float* c, const uint32_t* a, const uint32_t* b) {
    asm volatile(
        "mma.sync.aligned.m16n8k16.row.col.f32.bf16.bf16.f32 "
        "{%0,%1,%2,%3}, {%4,%5,%6,%7}, {%8,%9}, {%0,%1,%2,%3};"
        : "+f"(c[0]), "+f"(c[1]), "+f"(c[2]), "+f"(c[3])
        : "r"(a[0]), "r"(a[1]), "r"(a[2]), "r"(a[3]), "r"(b[0]), "r"(b[1]));
}
#endif

__global__ void __launch_bounds__(256)
gemm_kernel(float* __restrict__ out,
            const __nv_bfloat16* __restrict__ Aq, const __nv_bfloat16* __restrict__ Bq,
            const float* __restrict__ bias,
            const float* __restrict__ in_amax, const float* __restrict__ w_amax)
{
    extern __shared__ char smem[];
    const uint32_t sbase = smem_u32(smem);
    const int tid = threadIdx.x, wid = tid >> 5, lid = tid & 31;
    const int bn = blockIdx.x, bm = blockIdx.y;

    const __nv_bfloat16* gA = Aq + (size_t)bm * BM * K_DIM;
    const __nv_bfloat16* gB = Bq + (size_t)bn * BN * K_DIM;

    const float ax = fmaxf(__ldg(in_amax), AMAX_EPS_F);
    const float aw = fmaxf(__ldg(w_amax), AMAX_EPS_F);
    const float inv = (ax * aw) * (1.0f / (FP8_MAX_F * FP8_MAX_F));

#if HAS_TCGEN05
    // ================= tcgen05 path (sm_103a) =================
    if (wid == 0) {
        asm volatile("tcgen05.alloc.cta_group::1.sync.aligned.shared::cta.b32 [%0], %1;"
            :: "r"(sbase + 64), "r"(128u) : "memory");
    }
    if (tid == 0) {
        #pragma unroll
        for (int s = 0; s < NSTAGE; s++) MBARRIER_INIT(sbase + s * 8, 1);
    }
    __syncthreads();
    uint32_t tbase;
    asm volatile("ld.shared.b32 %0, [%1];" : "=r"(tbase) : "r"(sbase + 64));

    #pragma unroll
    for (int s = 0; s < NSTAGE; s++)
        load_stage(sbase + SMEM_HEAD + s * STAGE_BYTES, gA, gB, s, tid);

    int phase[NSTAGE];
    #pragma unroll
    for (int s = 0; s < NSTAGE; s++) phase[s] = 0;

    for (int kt = 0; kt < NKT; ++kt) {
        const int s = kt % NSTAGE;
        if (kt < NKT - 2)       asm volatile("cp.async.wait_group 2;\n" ::: "memory");
        else if (kt == NKT - 2) asm volatile("cp.async.wait_group 1;\n" ::: "memory");
        else                    asm volatile("cp.async.wait_group 0;\n" ::: "memory");
        asm volatile("fence.proxy.async.shared::cta;\n" ::: "memory");
        __syncthreads();

        if (wid == 0 && elect_one()) {
            const uint32_t stage_base = sbase + SMEM_HEAD + s * STAGE_BYTES;
            const uint64_t ad = MAKE_SMEM_DESC(stage_base);
            const uint64_t bd = MAKE_SMEM_DESC(stage_base + A_TILE_BYTES);
            #pragma unroll
            for (int k = 0; k < 4; k++) {   // K=16 per kind::f16 MMA, 32B = 2 desc units
                const uint32_t en = (uint32_t)((kt | k) != 0);
                mma_f16_ss(tbase, ad + k * 2, bd + k * 2, IDESC_F16, en);
            }
            asm volatile(
                "tcgen05.commit.cta_group::1.mbarrier::arrive::one.shared::cluster.b64 [%0];"
                :: "r"(sbase + s * 8) : "memory");
        }

        if (kt + NSTAGE < NKT) {
            MBARRIER_WAIT_PARITY(sbase + s * 8, phase[s]);
            phase[s] ^= 1;
            load_stage(sbase + SMEM_HEAD + s * STAGE_BYTES, gA, gB, kt + NSTAGE, tid);
        }
    }
    {
        const int sf = (NKT - 1) % NSTAGE;
        MBARRIER_WAIT_PARITY(sbase + sf * 8, phase[sf]);
    }
    asm volatile("tcgen05.fence::after_thread_sync;" ::: "memory");

    // epilogue: warps 0-3 cols 0..63, warps 4-7 cols 64..127; rows via (wid&3)
    {
        const int sub = wid & 3, half = wid >> 2;
        const int mrow = bm * BM + sub * 32 + lid;
        float* orow = out + (size_t)mrow * N_DIM + bn * BN + half * 64;
        const float* brow = bias + bn * BN + half * 64;
        #pragma unroll
        for (int cb = 0; cb < 64; cb += 32) {
            uint32_t r[32];
            TCGEN05_LD_32X32B_X32(r, tbase + half * 64 + cb);
            asm volatile("tcgen05.wait::ld.sync.aligned;" ::: "memory");
            #pragma unroll
            for (int q = 0; q < 8; q++) {
                float4 v;
                v.x = __uint_as_float(r[q*4+0]) * inv + __ldg(brow + cb + q*4+0);
                v.y = __uint_as_float(r[q*4+1]) * inv + __ldg(brow + cb + q*4+1);
                v.z = __uint_as_float(r[q*4+2]) * inv + __ldg(brow + cb + q*4+2);
                v.w = __uint_as_float(r[q*4+3]) * inv + __ldg(brow + cb + q*4+3);
                *reinterpret_cast<float4*>(orow + cb + q*4) = v;
            }
        }
    }
    __syncthreads();
    if (tid == 0) {
        #pragma unroll
        for (int s = 0; s < NSTAGE; s++)
            asm volatile("mbarrier.inval.shared.b64 [%0];" :: "r"(sbase + s * 8) : "memory");
    }
    __syncthreads();
    if (wid == 0) {
        asm volatile("tcgen05.relinquish_alloc_permit.cta_group::1.sync.aligned;");
        asm volatile("tcgen05.dealloc.cta_group::1.sync.aligned.b32 %0, %1;"
            :: "r"(tbase), "r"(128u));
    }
#else
    // ================= mma.sync fallback (plain sm_103) =================
    const int wr = wid >> 1, wc = wid & 1;   // 4 x 2 warp grid, warp tile 32x64
    float acc[2][8][4];
    #pragma unroll
    for (int i = 0; i < 2; i++)
        #pragma unroll
        for (int nb = 0; nb < 8; nb++)
            #pragma unroll
            for (int q = 0; q < 4; q++) acc[i][nb][q] = 0.0f;

    #pragma unroll
    for (int s = 0; s < NSTAGE; s++)
        load_stage(sbase + SMEM_HEAD + s * STAGE_BYTES, gA, gB, s, tid);

    for (int kt = 0; kt < NKT; ++kt) {
        if (kt < NKT - 2)       asm volatile("cp.async.wait_group 2;\n" ::: "memory");
        else if (kt == NKT - 2) asm volatile("cp.async.wait_group 1;\n" ::: "memory");
        else                    asm volatile("cp.async.wait_group 0;\n" ::: "memory");
        __syncthreads();

        const char* stA = smem + SMEM_HEAD + (kt % NSTAGE) * STAGE_BYTES;
        const char* stB = stA + A_TILE_BYTES;

        #pragma unroll
        for (int ks = 0; ks < 4; ks++) {    // 4 x k16 within BK=64
            uint32_t bfr[8][2];
            #pragma unroll
            for (int nb = 0; nb < 8; nb++) {
                const int n = wc * 64 + nb * 8 + (lid >> 2);
                uint32_t off = (uint32_t)(n * 128 + ks * 32 + (lid & 3) * 4);
                bfr[nb][0] = *(const uint32_t*)(stB + sw128(off));
                bfr[nb][1] = *(const uint32_t*)(stB + sw128(off + 16));
            }
            #pragma unroll
            for (int i = 0; i < 2; i++) {
                const int r0 = wr * 32 + i * 16 + (lid >> 2);
                uint32_t a[4];
                uint32_t off0 = (uint32_t)(r0 * 128 + ks * 32 + (lid & 3) * 4);
                uint32_t off1 = off0 + 8 * 128;
                a[0] = *(const uint32_t*)(stA + sw128(off0));
                a[1] = *(const uint32_t*)(stA + sw128(off1));
                a[2] = *(const uint32_t*)(stA + sw128(off0 + 16));
                a[3] = *(const uint32_t*)(stA + sw128(off1 + 16));
                #pragma unroll
                for (int nb = 0; nb < 8; nb++) mma_bf16(acc[i][nb], a, bfr[nb]);
            }
        }
        __syncthreads();
        if (kt + NSTAGE < NKT)
            load_stage(sbase + SMEM_HEAD + (kt % NSTAGE) * STAGE_BYTES, gA, gB,
                       kt + NSTAGE, tid);
    }

    // epilogue
    #pragma unroll
    for (int i = 0; i < 2; i++) {
        const int r0 = bm * BM + wr * 32 + i * 16 + (lid >> 2);
        #pragma unroll
        for (int nb = 0; nb < 8; nb++) {
            const int col = bn * BN + wc * 64 + nb * 8 + (lid & 3) * 2;
            const float b0 = __ldg(bias + col), b1 = __ldg(bias + col + 1);
            float2 v0 = {acc[i][nb][0] * inv + b0, acc[i][nb][1] * inv + b1};
            float2 v1 = {acc[i][nb][2] * inv + b0, acc[i][nb][3] * inv + b1};
            *reinterpret_cast<float2*>(out + (size_t)r0 * N_DIM + col) = v0;
            *reinterpret_cast<float2*>(out + (size_t)(r0 + 8) * N_DIM + col) = v1;
        }
    }
#endif
}

// ======================= launch =======================
extern "C" void kernel_launch(void* const* d_in, const int* in_sizes, int n_in,
                              void* d_out, int out_size)
{
    const float* x       = (const float*)d_in[0];
    const float* w       = (const float*)d_in[1];
    const float* bias    = (const float*)d_in[2];
    const float* in_amax = (const float*)d_in[3];
    const float* w_amax  = (const float*)d_in[4];
    float* out = (float*)d_out;

    __nv_bfloat16 *xq, *wq;
    unsigned int* ab;
    cudaGetSymbolAddress((void**)&xq, g_xq);
    cudaGetSymbolAddress((void**)&wq, g_wq);
    cudaGetSymbolAddress((void**)&ab, g_amax_bits);

    cudaFuncSetAttribute(gemm_kernel,
                         cudaFuncAttributeMaxDynamicSharedMemorySize, SMEM_TOTAL);

    init_amax_kernel<<<1, 32>>>(ab);
    quant_kernel<<<(M_DIM * K_DIM / 8) / 256, 256>>>(x, xq, in_amax, ab + 0);
    quant_kernel<<<(N_DIM * K_DIM / 8) / 256, 256>>>(w, wq, w_amax, ab + 1);
    finalize_amax_kernel<<<1, 32>>>(in_amax, w_amax, ab,
                                    out + (size_t)M_DIM * N_DIM);

    dim3 grid(N_DIM / BN, M_DIM / BM);   // (32, 64)
    gemm_kernel<<<grid, 256, SMEM_TOTAL>>>(out, xq, wq, bias, in_amax, w_amax);
}